// round 1
// baseline (speedup 1.0000x reference)
#include <cuda_runtime.h>
#include <cstdint>

// Problem constants
#define NB   16        // batch
#define CC   128       // channels
#define HH   112
#define WW   112
#define PP   98        // patches
#define PLANE (HH*WW)          // 12544 floats per (n,c) plane
#define PTS   (PP*16*16)       // 25088 sample points per image
#define CS    2                // channels per block (smem planes)
#define THREADS 512

__global__ __launch_bounds__(THREADS, 2)
void patches_kernel(const float* __restrict__ fm,
                    const float* __restrict__ grid,
                    float* __restrict__ out)
{
    extern __shared__ float s[];   // CS * PLANE floats = 100,352 B

    const int blk   = blockIdx.x;          // n * (CC/CS) + cblk
    const int n     = blk / (CC / CS);
    const int c0    = (blk % (CC / CS)) * CS;

    // ---- Stage CS channel planes into smem (coalesced float4 stream) ----
    {
        const float4* __restrict__ src =
            reinterpret_cast<const float4*>(fm + ((size_t)n * CC + c0) * PLANE);
        float4* dst = reinterpret_cast<float4*>(s);
        const int n4 = CS * PLANE / 4;      // 6272
        #pragma unroll 4
        for (int i = threadIdx.x; i < n4; i += THREADS)
            dst[i] = src[i];
    }
    __syncthreads();

    const float2* __restrict__ g =
        reinterpret_cast<const float2*>(grid) + (size_t)n * PTS;

    // out[n, p, c, hg, wg]  flat = ((n*PP + p)*CC + c)*256 + pix
    float* __restrict__ ob = out + (((size_t)n * PP) * CC + c0) * 256;

    for (int pt = threadIdx.x; pt < PTS; pt += THREADS) {
        const float2 xy = g[pt];

        // unnormalize (align_corners=False) + border clamp
        float x = fminf(fmaxf(fmaf(xy.x + 1.0f, 56.0f, -0.5f), 0.0f), 111.0f);
        float y = fminf(fmaxf(fmaf(xy.y + 1.0f, 56.0f, -0.5f), 0.0f), 111.0f);

        const float xf = floorf(x);
        const float yf = floorf(y);
        const float wx = x - xf;
        const float wy = y - yf;

        const int x0 = (int)xf;
        const int y0 = (int)yf;
        const int x1 = min(x0 + 1, WW - 1);
        const int y1 = min(y0 + 1, HH - 1);

        const int b00 = y0 * WW + x0;
        const int b01 = y0 * WW + x1;
        const int b10 = y1 * WW + x0;
        const int b11 = y1 * WW + x1;

        const float omwx = 1.0f - wx;
        const float omwy = 1.0f - wy;
        const float w00 = omwy * omwx;
        const float w01 = omwy * wx;
        const float w10 = wy * omwx;
        const float w11 = wy * wx;

        const int p   = pt >> 8;
        const int pix = pt & 255;
        float* __restrict__ o = ob + (size_t)p * (CC * 256) + pix;

        #pragma unroll
        for (int cc = 0; cc < CS; cc++) {
            const float* __restrict__ sp = s + cc * PLANE;
            float v;
            v = sp[b00] * w00;
            v = fmaf(sp[b01], w01, v);
            v = fmaf(sp[b10], w10, v);
            v = fmaf(sp[b11], w11, v);
            o[cc * 256] = v;
        }
    }
}

extern "C" void kernel_launch(void* const* d_in, const int* in_sizes, int n_in,
                              void* d_out, int out_size)
{
    const float* fm   = (const float*)d_in[0];   // [16,128,112,112] f32
    const float* grid = (const float*)d_in[1];   // [16,98,16,16,2]  f32
    float* out        = (float*)d_out;           // [16,98,128,16,16] f32

    const int smem = CS * PLANE * sizeof(float); // 100,352 B (needs opt-in)
    cudaFuncSetAttribute(patches_kernel,
                         cudaFuncAttributeMaxDynamicSharedMemorySize, smem);

    const int blocks = NB * (CC / CS);           // 1024
    patches_kernel<<<blocks, THREADS, smem>>>(fm, grid, out);
}